// round 8
// baseline (speedup 1.0000x reference)
#include <cuda_runtime.h>
#include <cstdint>

#define N_NODES 100000
#define N_EDGES 1600000
#define D 128
#define TILE_M 64
#define SCAN_BLOCK 512
#define NB_SCAN ((N_NODES + SCAN_BLOCK - 1) / SCAN_BLOCK)   // 196

// ---- device scratch (allocation-free rule: __device__ globals) ----
__device__ float g_support[(size_t)N_NODES * D];   // x @ W
__device__ int   g_count[N_NODES];                 // histogram of dst
__device__ int   g_offset[N_NODES + 1];            // CSR row offsets
__device__ int   g_cursor[N_NODES];                // scatter cursors
__device__ int   g_blocksum[NB_SCAN];              // scan partials
__device__ uint2 g_edges[N_EDGES];                 // {src, float_bits(w)} sorted by dst

static_assert(NB_SCAN <= 256, "scan2 single block assumption");

// ---------------------------------------------------------------------------
// CSR build step 1: histogram of edge_dst
// ---------------------------------------------------------------------------
__global__ void hist_kernel(const int* __restrict__ edst)
{
    int i = blockIdx.x * blockDim.x + threadIdx.x;
    int stride = gridDim.x * blockDim.x;
    for (; i < N_EDGES; i += stride)
        atomicAdd(&g_count[edst[i]], 1);
}

// ---------------------------------------------------------------------------
// CSR build step 2a: per-block exclusive scan
// ---------------------------------------------------------------------------
__global__ void scan1_kernel()
{
    __shared__ int warp_sums[SCAN_BLOCK / 32];
    int tid = threadIdx.x;
    int gid = blockIdx.x * SCAN_BLOCK + tid;
    int v = (gid < N_NODES) ? g_count[gid] : 0;

    int x = v;
    #pragma unroll
    for (int o = 1; o < 32; o <<= 1) {
        int y = __shfl_up_sync(0xFFFFFFFFu, x, o);
        if ((tid & 31) >= o) x += y;
    }
    if ((tid & 31) == 31) warp_sums[tid >> 5] = x;
    __syncthreads();
    if (tid < 32) {
        const int nw = SCAN_BLOCK / 32;
        int s = (tid < nw) ? warp_sums[tid] : 0;
        #pragma unroll
        for (int o = 1; o < 32; o <<= 1) {
            int y = __shfl_up_sync(0xFFFFFFFFu, s, o);
            if (tid >= o) s += y;
        }
        if (tid < nw) warp_sums[tid] = s;
    }
    __syncthreads();
    int base = (tid >= 32) ? warp_sums[(tid >> 5) - 1] : 0;
    int incl = x + base;
    if (gid < N_NODES) g_offset[gid] = incl - v;
    if (tid == SCAN_BLOCK - 1) g_blocksum[blockIdx.x] = incl;
}

// ---------------------------------------------------------------------------
// CSR build step 2b: exclusive scan of block totals (1 block)
// ---------------------------------------------------------------------------
__global__ void scan2_kernel()
{
    __shared__ int sh[256];
    int tid = threadIdx.x;
    int v = (tid < NB_SCAN) ? g_blocksum[tid] : 0;
    sh[tid] = v;
    __syncthreads();
    #pragma unroll
    for (int o = 1; o < 256; o <<= 1) {
        int y = (tid >= o) ? sh[tid - o] : 0;
        __syncthreads();
        sh[tid] += y;
        __syncthreads();
    }
    if (tid < NB_SCAN) g_blocksum[tid] = sh[tid] - v;
}

// ---------------------------------------------------------------------------
// CSR build step 2c: add block bases, init cursors, cap offsets
// ---------------------------------------------------------------------------
__global__ void scan3_kernel()
{
    int gid = blockIdx.x * SCAN_BLOCK + threadIdx.x;
    if (gid < N_NODES) {
        int o = g_offset[gid] + g_blocksum[blockIdx.x];
        g_offset[gid] = o;
        g_cursor[gid] = o;
    }
    if (gid == 0) g_offset[N_NODES] = N_EDGES;
}

// ---------------------------------------------------------------------------
// CSR build step 3: scatter edges into dst-sorted order
// ---------------------------------------------------------------------------
__global__ void scatter_kernel(const int* __restrict__ esrc,
                               const int* __restrict__ edst,
                               const float* __restrict__ ew)
{
    int i = blockIdx.x * blockDim.x + threadIdx.x;
    int stride = gridDim.x * blockDim.x;
    for (; i < N_EDGES; i += stride) {
        int d = edst[i];
        int pos = atomicAdd(&g_cursor[d], 1);
        g_edges[pos] = make_uint2((unsigned)esrc[i], __float_as_uint(ew[i]));
    }
}

// ---------------------------------------------------------------------------
// Packed-f32x2 GEMM: support = x @ W.
// K paired into f32x2 lanes: acc.lo accumulates even-k, acc.hi odd-k.
// A operand (x[r][k], x[r][k+1]) is a natural contiguous float2 load (no pack);
// B operand (w[k][c], w[k+1][c]) packed once per 2-k step, reused by 8 rows.
// Block 256 threads: TILE_M=64 rows x 128 cols; thread = 8 rows x 4 cols.
// ---------------------------------------------------------------------------
__device__ __forceinline__ unsigned long long pack_f32x2(float lo, float hi)
{
    unsigned long long r;
    asm("mov.b64 %0, {%1, %2};" : "=l"(r) : "f"(lo), "f"(hi));
    return r;
}

__device__ __forceinline__ void fma_f32x2(unsigned long long& d,
                                          unsigned long long a,
                                          unsigned long long b)
{
    asm("fma.rn.f32x2 %0, %1, %2, %0;" : "+l"(d) : "l"(a), "l"(b));
}

__global__ void gemm_kernel(const float* __restrict__ x,
                            const float* __restrict__ W,
                            float* __restrict__ support,
                            int n_rows)
{
    extern __shared__ float smem[];
    float* Ws = smem;                 // [D][D]      64 KB
    float* xs = smem + D * D;         // [TILE_M][D] 32 KB

    int tid = threadIdx.x;
    int m0 = blockIdx.x * TILE_M;

    // Load W (coalesced float4)
    {
        const float4* Wg = (const float4*)W;
        float4* Wsh = (float4*)Ws;
        #pragma unroll
        for (int i = 0; i < (D * D / 4) / 256; i++)
            Wsh[tid + i * 256] = Wg[tid + i * 256];
    }
    // Load x tile (coalesced float4, zero-padded)
    {
        const float4* xg = (const float4*)x;
        float4* xsh = (float4*)xs;
        #pragma unroll
        for (int i = 0; i < (TILE_M * (D / 4)) / 256; i++) {
            int idx = tid + i * 256;
            int r = idx >> 5;
            int c4 = idx & 31;
            int row = m0 + r;
            float4 v = make_float4(0.f, 0.f, 0.f, 0.f);
            if (row < n_rows) v = xg[(size_t)row * (D / 4) + c4];
            xsh[(size_t)r * (D / 4) + c4] = v;
        }
    }
    __syncthreads();

    int cg = tid & 31;    // cols cg*4..cg*4+3 (lane-consecutive -> conflict-free LDS.128)
    int rg = tid >> 5;    // rows rg*8..rg*8+7 (warp-uniform -> LDS broadcast)

    unsigned long long acc2[8][4];
    #pragma unroll
    for (int r = 0; r < 8; r++)
        #pragma unroll
        for (int c = 0; c < 4; c++) acc2[r][c] = 0ull;

    const float* xrow = xs + (size_t)(rg * 8) * D;

    #pragma unroll 2
    for (int k = 0; k < D; k += 2) {
        // B pairs for 4 columns: (w[k][c], w[k+1][c])
        float4 w0 = *(const float4*)&Ws[(size_t)k * D + cg * 4];
        float4 w1 = *(const float4*)&Ws[(size_t)(k + 1) * D + cg * 4];
        unsigned long long b0 = pack_f32x2(w0.x, w1.x);
        unsigned long long b1 = pack_f32x2(w0.y, w1.y);
        unsigned long long b2 = pack_f32x2(w0.z, w1.z);
        unsigned long long b3 = pack_f32x2(w0.w, w1.w);

        #pragma unroll
        for (int r = 0; r < 8; r++) {
            // natural f32x2: (x[r][k], x[r][k+1]) contiguous in smem
            unsigned long long a = *(const unsigned long long*)&xrow[(size_t)r * D + k];
            fma_f32x2(acc2[r][0], a, b0);
            fma_f32x2(acc2[r][1], a, b1);
            fma_f32x2(acc2[r][2], a, b2);
            fma_f32x2(acc2[r][3], a, b3);
        }
    }

    // Epilogue: lo + hi (even-k partial + odd-k partial)
    #pragma unroll
    for (int r = 0; r < 8; r++) {
        int row = m0 + rg * 8 + r;
        if (row < n_rows) {
            float o[4];
            #pragma unroll
            for (int c = 0; c < 4; c++) {
                float lo, hi;
                asm("mov.b64 {%0, %1}, %2;" : "=f"(lo), "=f"(hi) : "l"(acc2[r][c]));
                o[c] = lo + hi;
            }
            *(float4*)&support[(size_t)row * D + cg * 4] =
                make_float4(o[0], o[1], o[2], o[3]);
        }
    }
}

// ---------------------------------------------------------------------------
// Gather SpMM: one warp per dst node. out[d] = bias + sum w_e * support[src_e]
// ---------------------------------------------------------------------------
__global__ void gather_kernel(const float* __restrict__ bias,
                              float* __restrict__ out)
{
    int warp = (blockIdx.x * blockDim.x + threadIdx.x) >> 5;
    int lane = threadIdx.x & 31;
    if (warp >= N_NODES) return;

    int start = g_offset[warp];
    int end   = g_offset[warp + 1];

    const float4* sup4 = (const float4*)g_support;
    float4 acc = __ldg(&((const float4*)bias)[lane]);

    for (int i = start; i < end; i += 32) {
        int n = end - i;
        if (n > 32) n = 32;
        uint2 em = make_uint2(0u, 0u);
        if (lane < n) em = g_edges[i + lane];
        for (int j = 0; j < n; j++) {
            unsigned s = __shfl_sync(0xFFFFFFFFu, em.x, j);
            float    w = __uint_as_float(__shfl_sync(0xFFFFFFFFu, em.y, j));
            float4 v = sup4[(size_t)s * (D / 4) + lane];
            acc.x += w * v.x;
            acc.y += w * v.y;
            acc.z += w * v.z;
            acc.w += w * v.w;
        }
    }
    ((float4*)out)[(size_t)warp * (D / 4) + lane] = acc;
}

// ---------------------------------------------------------------------------
// Launch with fork/join: CSR build (side stream) overlaps GEMM (main stream);
// both join before gather.
// ---------------------------------------------------------------------------
extern "C" void kernel_launch(void* const* d_in, const int* in_sizes, int n_in,
                              void* d_out, int out_size)
{
    const float* x    = (const float*)d_in[0];
    const int*   esrc = (const int*)d_in[1];
    const int*   edst = (const int*)d_in[2];
    const float* ew   = (const float*)d_in[3];
    const float* W    = (const float*)d_in[4];
    const float* bias = (const float*)d_in[5];
    float* out = (float*)d_out;

    void* countPtr;
    cudaGetSymbolAddress(&countPtr, g_count);
    float* support;
    cudaGetSymbolAddress((void**)&support, g_support);

    cudaStream_t main_s = 0;
    cudaStream_t side_s;
    cudaStreamCreateWithFlags(&side_s, cudaStreamNonBlocking);
    cudaEvent_t ev_fork, ev_join;
    cudaEventCreateWithFlags(&ev_fork, cudaEventDisableTiming);
    cudaEventCreateWithFlags(&ev_join, cudaEventDisableTiming);

    // ---- fork ----
    cudaEventRecord(ev_fork, main_s);
    cudaStreamWaitEvent(side_s, ev_fork, 0);

    // side stream: CSR build chain
    cudaMemsetAsync(countPtr, 0, N_NODES * sizeof(int), side_s);
    hist_kernel<<<1024, 256, 0, side_s>>>(edst);
    scan1_kernel<<<NB_SCAN, SCAN_BLOCK, 0, side_s>>>();
    scan2_kernel<<<1, 256, 0, side_s>>>();
    scan3_kernel<<<NB_SCAN, SCAN_BLOCK, 0, side_s>>>();
    scatter_kernel<<<1024, 256, 0, side_s>>>(esrc, edst, ew);
    cudaEventRecord(ev_join, side_s);

    // main stream: dense projection (packed f32x2 FFMA GEMM)
    {
        static const int smem_bytes = (D * D + TILE_M * D) * (int)sizeof(float); // 96 KB
        cudaFuncSetAttribute(gemm_kernel, cudaFuncAttributeMaxDynamicSharedMemorySize, smem_bytes);
        int blocks = (N_NODES + TILE_M - 1) / TILE_M;
        gemm_kernel<<<blocks, 256, smem_bytes, main_s>>>(x, W, support, N_NODES);
    }

    // ---- join ----
    cudaStreamWaitEvent(main_s, ev_join, 0);

    // gather SpMM + bias
    {
        int warps_per_block = 8;
        int blocks = (N_NODES + warps_per_block - 1) / warps_per_block;
        gather_kernel<<<blocks, 256, 0, main_s>>>(bias, out);
    }
}

// round 11
// speedup vs baseline: 1.1524x; 1.1524x over previous
#include <cuda_runtime.h>
#include <cstdint>

#define N_NODES 100000
#define N_EDGES 1600000
#define D 128
#define TILE_M 64
#define SCAN_BLOCK 512
#define NB_SCAN ((N_NODES + SCAN_BLOCK - 1) / SCAN_BLOCK)   // 196

// ---- device scratch (allocation-free rule: __device__ globals) ----
__device__ float g_support[(size_t)N_NODES * D];   // x @ W
__device__ int   g_count[N_NODES];                 // histogram of dst
__device__ int   g_offset[N_NODES + 1];            // CSR row offsets
__device__ int   g_cursor[N_NODES];                // scatter cursors
__device__ int   g_blocksum[NB_SCAN];              // scan partials
__device__ uint2 g_edges[N_EDGES];                 // {src, float_bits(w)} sorted by dst

static_assert(NB_SCAN <= 256, "scan2 single block assumption");

// ---------------------------------------------------------------------------
// CSR build step 1: histogram of edge_dst
// ---------------------------------------------------------------------------
__global__ void hist_kernel(const int* __restrict__ edst)
{
    int i = blockIdx.x * blockDim.x + threadIdx.x;
    int stride = gridDim.x * blockDim.x;
    for (; i < N_EDGES; i += stride)
        atomicAdd(&g_count[edst[i]], 1);
}

// ---------------------------------------------------------------------------
// CSR build step 2a: per-block exclusive scan
// ---------------------------------------------------------------------------
__global__ void scan1_kernel()
{
    __shared__ int warp_sums[SCAN_BLOCK / 32];
    int tid = threadIdx.x;
    int gid = blockIdx.x * SCAN_BLOCK + tid;
    int v = (gid < N_NODES) ? g_count[gid] : 0;

    int x = v;
    #pragma unroll
    for (int o = 1; o < 32; o <<= 1) {
        int y = __shfl_up_sync(0xFFFFFFFFu, x, o);
        if ((tid & 31) >= o) x += y;
    }
    if ((tid & 31) == 31) warp_sums[tid >> 5] = x;
    __syncthreads();
    if (tid < 32) {
        const int nw = SCAN_BLOCK / 32;
        int s = (tid < nw) ? warp_sums[tid] : 0;
        #pragma unroll
        for (int o = 1; o < 32; o <<= 1) {
            int y = __shfl_up_sync(0xFFFFFFFFu, s, o);
            if (tid >= o) s += y;
        }
        if (tid < nw) warp_sums[tid] = s;
    }
    __syncthreads();
    int base = (tid >= 32) ? warp_sums[(tid >> 5) - 1] : 0;
    int incl = x + base;
    if (gid < N_NODES) g_offset[gid] = incl - v;
    if (tid == SCAN_BLOCK - 1) g_blocksum[blockIdx.x] = incl;
}

// ---------------------------------------------------------------------------
// CSR build step 2b: exclusive scan of block totals (1 block)
// ---------------------------------------------------------------------------
__global__ void scan2_kernel()
{
    __shared__ int sh[256];
    int tid = threadIdx.x;
    int v = (tid < NB_SCAN) ? g_blocksum[tid] : 0;
    sh[tid] = v;
    __syncthreads();
    #pragma unroll
    for (int o = 1; o < 256; o <<= 1) {
        int y = (tid >= o) ? sh[tid - o] : 0;
        __syncthreads();
        sh[tid] += y;
        __syncthreads();
    }
    if (tid < NB_SCAN) g_blocksum[tid] = sh[tid] - v;
}

// ---------------------------------------------------------------------------
// CSR build step 2c: add block bases, init cursors, cap offsets
// ---------------------------------------------------------------------------
__global__ void scan3_kernel()
{
    int gid = blockIdx.x * SCAN_BLOCK + threadIdx.x;
    if (gid < N_NODES) {
        int o = g_offset[gid] + g_blocksum[blockIdx.x];
        g_offset[gid] = o;
        g_cursor[gid] = o;
    }
    if (gid == 0) g_offset[N_NODES] = N_EDGES;
}

// ---------------------------------------------------------------------------
// CSR build step 3: scatter edges into dst-sorted order
// ---------------------------------------------------------------------------
__global__ void scatter_kernel(const int* __restrict__ esrc,
                               const int* __restrict__ edst,
                               const float* __restrict__ ew)
{
    int i = blockIdx.x * blockDim.x + threadIdx.x;
    int stride = gridDim.x * blockDim.x;
    for (; i < N_EDGES; i += stride) {
        int d = edst[i];
        int pos = atomicAdd(&g_cursor[d], 1);
        g_edges[pos] = make_uint2((unsigned)esrc[i], __float_as_uint(ew[i]));
    }
}

// ---------------------------------------------------------------------------
// GEMM: support = x @ W  (scalar fp32 FFMA — measured at the chip issue floor,
// 95 us; faster than mma.sync-tf32 / f32x2 on this part, tcgen05 unavailable
// because the harness compiles PTX at target sm_103 (non-'a')).
// Block 256 threads: TILE_M=64 rows x 128 cols; thread = 8 rows x 4 cols.
// ---------------------------------------------------------------------------
__global__ void gemm_kernel(const float* __restrict__ x,
                            const float* __restrict__ W,
                            float* __restrict__ support,
                            int n_rows)
{
    extern __shared__ float smem[];
    float* Ws = smem;                 // [D][D]      64 KB
    float* xs = smem + D * D;         // [TILE_M][D] 32 KB

    int tid = threadIdx.x;
    int m0 = blockIdx.x * TILE_M;

    // Load W (128x128 = 4096 float4), coalesced.
    {
        const float4* Wg = (const float4*)W;
        float4* Wsh = (float4*)Ws;
        #pragma unroll
        for (int i = 0; i < (D * D / 4) / 256; i++)
            Wsh[tid + i * 256] = Wg[tid + i * 256];
    }
    // Load x tile (64 rows x 32 float4), coalesced, zero-padded.
    {
        const float4* xg = (const float4*)x;
        float4* xsh = (float4*)xs;
        #pragma unroll
        for (int i = 0; i < (TILE_M * (D / 4)) / 256; i++) {
            int idx = tid + i * 256;
            int r = idx >> 5;
            int c4 = idx & 31;
            int row = m0 + r;
            float4 v = make_float4(0.f, 0.f, 0.f, 0.f);
            if (row < n_rows) v = xg[(size_t)row * (D / 4) + c4];
            xsh[(size_t)r * (D / 4) + c4] = v;
        }
    }
    __syncthreads();

    int cg = tid & 31;    // cols cg*4..cg*4+3 (lane-consecutive -> conflict-free LDS.128)
    int rg = tid >> 5;    // rows rg*8..rg*8+7 (warp-uniform -> LDS broadcast)

    float acc[8][4];
    #pragma unroll
    for (int r = 0; r < 8; r++)
        #pragma unroll
        for (int c = 0; c < 4; c++) acc[r][c] = 0.f;

    const float* xrow = xs + (size_t)(rg * 8) * D;

    #pragma unroll 4
    for (int k = 0; k < D; k++) {
        float4 wv = *(const float4*)&Ws[(size_t)k * D + cg * 4];
        #pragma unroll
        for (int r = 0; r < 8; r++) {
            float xv = xrow[(size_t)r * D + k];
            acc[r][0] += xv * wv.x;
            acc[r][1] += xv * wv.y;
            acc[r][2] += xv * wv.z;
            acc[r][3] += xv * wv.w;
        }
    }

    #pragma unroll
    for (int r = 0; r < 8; r++) {
        int row = m0 + rg * 8 + r;
        if (row < n_rows)
            *(float4*)&support[(size_t)row * D + cg * 4] =
                make_float4(acc[r][0], acc[r][1], acc[r][2], acc[r][3]);
    }
}

// ---------------------------------------------------------------------------
// Gather SpMM: one warp per dst node. out[d] = bias + sum w_e * support[src_e]
// ---------------------------------------------------------------------------
__global__ void gather_kernel(const float* __restrict__ bias,
                              float* __restrict__ out)
{
    int warp = (blockIdx.x * blockDim.x + threadIdx.x) >> 5;
    int lane = threadIdx.x & 31;
    if (warp >= N_NODES) return;

    int start = g_offset[warp];
    int end   = g_offset[warp + 1];

    const float4* sup4 = (const float4*)g_support;
    float4 acc = __ldg(&((const float4*)bias)[lane]);

    for (int i = start; i < end; i += 32) {
        int n = end - i;
        if (n > 32) n = 32;
        uint2 em = make_uint2(0u, 0u);
        if (lane < n) em = g_edges[i + lane];
        for (int j = 0; j < n; j++) {
            unsigned s = __shfl_sync(0xFFFFFFFFu, em.x, j);
            float    w = __uint_as_float(__shfl_sync(0xFFFFFFFFu, em.y, j));
            float4 v = sup4[(size_t)s * (D / 4) + lane];
            acc.x += w * v.x;
            acc.y += w * v.y;
            acc.z += w * v.z;
            acc.w += w * v.w;
        }
    }
    ((float4*)out)[(size_t)warp * (D / 4) + lane] = acc;
}

// ---------------------------------------------------------------------------
// Launch with fork/join: CSR build (side stream) overlaps the GEMM (main
// stream); join before gather. Critical path = max(CSR, GEMM) + gather.
// ---------------------------------------------------------------------------
extern "C" void kernel_launch(void* const* d_in, const int* in_sizes, int n_in,
                              void* d_out, int out_size)
{
    const float* x    = (const float*)d_in[0];
    const int*   esrc = (const int*)d_in[1];
    const int*   edst = (const int*)d_in[2];
    const float* ew   = (const float*)d_in[3];
    const float* W    = (const float*)d_in[4];
    const float* bias = (const float*)d_in[5];
    float* out = (float*)d_out;

    void* countPtr;
    cudaGetSymbolAddress(&countPtr, g_count);
    float* support;
    cudaGetSymbolAddress((void**)&support, g_support);

    cudaStream_t main_s = 0;
    cudaStream_t side_s;
    cudaStreamCreateWithFlags(&side_s, cudaStreamNonBlocking);
    cudaEvent_t ev_fork, ev_join;
    cudaEventCreateWithFlags(&ev_fork, cudaEventDisableTiming);
    cudaEventCreateWithFlags(&ev_join, cudaEventDisableTiming);

    // ---- fork ----
    cudaEventRecord(ev_fork, main_s);
    cudaStreamWaitEvent(side_s, ev_fork, 0);

    // side stream: CSR build chain
    cudaMemsetAsync(countPtr, 0, N_NODES * sizeof(int), side_s);
    hist_kernel<<<1024, 256, 0, side_s>>>(edst);
    scan1_kernel<<<NB_SCAN, SCAN_BLOCK, 0, side_s>>>();
    scan2_kernel<<<1, 256, 0, side_s>>>();
    scan3_kernel<<<NB_SCAN, SCAN_BLOCK, 0, side_s>>>();
    scatter_kernel<<<1024, 256, 0, side_s>>>(esrc, edst, ew);
    cudaEventRecord(ev_join, side_s);

    // main stream: dense projection (scalar FFMA GEMM, at issue floor)
    {
        static const int smem_bytes = (D * D + TILE_M * D) * (int)sizeof(float); // 96 KB
        cudaFuncSetAttribute(gemm_kernel, cudaFuncAttributeMaxDynamicSharedMemorySize, smem_bytes);
        int blocks = (N_NODES + TILE_M - 1) / TILE_M;
        gemm_kernel<<<blocks, 256, smem_bytes, main_s>>>(x, W, support, N_NODES);
    }

    // ---- join ----
    cudaStreamWaitEvent(main_s, ev_join, 0);

    // gather SpMM + bias
    {
        int warps_per_block = 8;
        int blocks = (N_NODES + warps_per_block - 1) / warps_per_block;
        gather_kernel<<<blocks, 256, 0, main_s>>>(bias, out);
    }
}

// round 15
// speedup vs baseline: 1.1898x; 1.0325x over previous
#include <cuda_runtime.h>
#include <cstdint>

#define N_NODES 100000
#define N_EDGES 1600000
#define D 128
#define TILE_M 64
#define N_TILES ((N_NODES + TILE_M - 1) / TILE_M)   // 1563
#define PERSIST_BLOCKS 304                          // 2 CTAs x 152 SMs (GB300)
#define SCAN_BLOCK 512
#define NB_SCAN ((N_NODES + SCAN_BLOCK - 1) / SCAN_BLOCK)   // 196

// ---- device scratch (allocation-free rule: __device__ globals) ----
__device__ float g_support[(size_t)N_NODES * D];   // x @ W
__device__ int   g_count[N_NODES];                 // histogram of dst
__device__ int   g_offset[N_NODES + 1];            // CSR row offsets
__device__ int   g_cursor[N_NODES];                // scatter cursors
__device__ int   g_blocksum[NB_SCAN];              // scan partials
__device__ uint2 g_edges[N_EDGES];                 // {src, float_bits(w)} sorted by dst

static_assert(NB_SCAN <= 256, "scan2 single block assumption");

// ---------------------------------------------------------------------------
// CSR build step 1: histogram of edge_dst
// ---------------------------------------------------------------------------
__global__ void hist_kernel(const int* __restrict__ edst)
{
    int i = blockIdx.x * blockDim.x + threadIdx.x;
    int stride = gridDim.x * blockDim.x;
    for (; i < N_EDGES; i += stride)
        atomicAdd(&g_count[edst[i]], 1);
}

// ---------------------------------------------------------------------------
// CSR build step 2a: per-block exclusive scan
// ---------------------------------------------------------------------------
__global__ void scan1_kernel()
{
    __shared__ int warp_sums[SCAN_BLOCK / 32];
    int tid = threadIdx.x;
    int gid = blockIdx.x * SCAN_BLOCK + tid;
    int v = (gid < N_NODES) ? g_count[gid] : 0;

    int x = v;
    #pragma unroll
    for (int o = 1; o < 32; o <<= 1) {
        int y = __shfl_up_sync(0xFFFFFFFFu, x, o);
        if ((tid & 31) >= o) x += y;
    }
    if ((tid & 31) == 31) warp_sums[tid >> 5] = x;
    __syncthreads();
    if (tid < 32) {
        const int nw = SCAN_BLOCK / 32;
        int s = (tid < nw) ? warp_sums[tid] : 0;
        #pragma unroll
        for (int o = 1; o < 32; o <<= 1) {
            int y = __shfl_up_sync(0xFFFFFFFFu, s, o);
            if (tid >= o) s += y;
        }
        if (tid < nw) warp_sums[tid] = s;
    }
    __syncthreads();
    int base = (tid >= 32) ? warp_sums[(tid >> 5) - 1] : 0;
    int incl = x + base;
    if (gid < N_NODES) g_offset[gid] = incl - v;
    if (tid == SCAN_BLOCK - 1) g_blocksum[blockIdx.x] = incl;
}

// ---------------------------------------------------------------------------
// CSR build step 2b: exclusive scan of block totals (1 block)
// ---------------------------------------------------------------------------
__global__ void scan2_kernel()
{
    __shared__ int sh[256];
    int tid = threadIdx.x;
    int v = (tid < NB_SCAN) ? g_blocksum[tid] : 0;
    sh[tid] = v;
    __syncthreads();
    #pragma unroll
    for (int o = 1; o < 256; o <<= 1) {
        int y = (tid >= o) ? sh[tid - o] : 0;
        __syncthreads();
        sh[tid] += y;
        __syncthreads();
    }
    if (tid < NB_SCAN) g_blocksum[tid] = sh[tid] - v;
}

// ---------------------------------------------------------------------------
// CSR build step 2c: add block bases, init cursors, cap offsets
// ---------------------------------------------------------------------------
__global__ void scan3_kernel()
{
    int gid = blockIdx.x * SCAN_BLOCK + threadIdx.x;
    if (gid < N_NODES) {
        int o = g_offset[gid] + g_blocksum[blockIdx.x];
        g_offset[gid] = o;
        g_cursor[gid] = o;
    }
    if (gid == 0) g_offset[N_NODES] = N_EDGES;
}

// ---------------------------------------------------------------------------
// CSR build step 3: scatter edges into dst-sorted order
// ---------------------------------------------------------------------------
__global__ void scatter_kernel(const int* __restrict__ esrc,
                               const int* __restrict__ edst,
                               const float* __restrict__ ew)
{
    int i = blockIdx.x * blockDim.x + threadIdx.x;
    int stride = gridDim.x * blockDim.x;
    for (; i < N_EDGES; i += stride) {
        int d = edst[i];
        int pos = atomicAdd(&g_cursor[d], 1);
        g_edges[pos] = make_uint2((unsigned)esrc[i], __float_as_uint(ew[i]));
    }
}

// ---------------------------------------------------------------------------
// Persistent GEMM: support = x @ W.
// Grid = PERSIST_BLOCKS (2/SM). Each CTA loads W into smem ONCE, then
// self-schedules tiles (tile = bid, bid+grid, ...), prefetching the next
// x-tile into registers while computing the current one from smem.
// Per-tile: 256 threads, 64 rows x 128 cols; thread = 8 rows x 4 cols.
// ---------------------------------------------------------------------------
__global__ void __launch_bounds__(256)
gemm_persist_kernel(const float* __restrict__ x,
                    const float* __restrict__ W,
                    float* __restrict__ support)
{
    extern __shared__ float smem[];
    float* Ws = smem;                 // [D][D]      64 KB
    float* xs = smem + D * D;         // [TILE_M][D] 32 KB

    int tid = threadIdx.x;
    int cg = tid & 31;    // cols cg*4..cg*4+3 (lane-consecutive -> LDS.128 conflict-free)
    int rg = tid >> 5;    // rows rg*8..rg*8+7 (warp-uniform -> LDS broadcast)

    // Load W once (128x128 = 4096 float4), coalesced.
    {
        const float4* Wg = (const float4*)W;
        float4* Wsh = (float4*)Ws;
        #pragma unroll
        for (int i = 0; i < 16; i++)
            Wsh[tid + i * 256] = Wg[tid + i * 256];
    }

    const float4* xg = (const float4*)x;
    float4* xs4 = (float4*)xs;

    // Prefetch first tile into registers (8 float4 per thread).
    float4 pre[8];
    int tile = blockIdx.x;
    if (tile < N_TILES) {
        #pragma unroll
        for (int i = 0; i < 8; i++) {
            int idx = tid + i * 256;          // 0..2047
            int r = idx >> 5, c4 = idx & 31;
            int row = tile * TILE_M + r;
            pre[i] = (row < N_NODES) ? xg[(size_t)row * 32 + c4]
                                     : make_float4(0.f, 0.f, 0.f, 0.f);
        }
    }

    for (; tile < N_TILES; tile += PERSIST_BLOCKS) {
        // prior compute (and the W load on iter 0) must finish before xs store
        __syncthreads();
        #pragma unroll
        for (int i = 0; i < 8; i++)
            xs4[tid + i * 256] = pre[i];
        __syncthreads();

        // Prefetch next tile (gmem latency hides under the FFMA block below).
        int ntile = tile + PERSIST_BLOCKS;
        if (ntile < N_TILES) {
            #pragma unroll
            for (int i = 0; i < 8; i++) {
                int idx = tid + i * 256;
                int r = idx >> 5, c4 = idx & 31;
                int row = ntile * TILE_M + r;
                pre[i] = (row < N_NODES) ? xg[(size_t)row * 32 + c4]
                                         : make_float4(0.f, 0.f, 0.f, 0.f);
            }
        }

        // Compute 64x128 tile.
        float acc[8][4];
        #pragma unroll
        for (int r = 0; r < 8; r++)
            #pragma unroll
            for (int c = 0; c < 4; c++) acc[r][c] = 0.f;

        const float* xrow = xs + (size_t)(rg * 8) * D;

        #pragma unroll 4
        for (int k = 0; k < D; k++) {
            float4 wv = *(const float4*)&Ws[(size_t)k * D + cg * 4];
            #pragma unroll
            for (int r = 0; r < 8; r++) {
                float xv = xrow[(size_t)r * D + k];
                acc[r][0] += xv * wv.x;
                acc[r][1] += xv * wv.y;
                acc[r][2] += xv * wv.z;
                acc[r][3] += xv * wv.w;
            }
        }

        int m0 = tile * TILE_M;
        #pragma unroll
        for (int r = 0; r < 8; r++) {
            int row = m0 + rg * 8 + r;
            if (row < N_NODES)
                *(float4*)&support[(size_t)row * D + cg * 4] =
                    make_float4(acc[r][0], acc[r][1], acc[r][2], acc[r][3]);
        }
    }
}

// ---------------------------------------------------------------------------
// Gather SpMM: one warp per dst node. out[d] = bias + sum w_e * support[src_e]
// ---------------------------------------------------------------------------
__global__ void gather_kernel(const float* __restrict__ bias,
                              float* __restrict__ out)
{
    int warp = (blockIdx.x * blockDim.x + threadIdx.x) >> 5;
    int lane = threadIdx.x & 31;
    if (warp >= N_NODES) return;

    int start = g_offset[warp];
    int end   = g_offset[warp + 1];

    const float4* sup4 = (const float4*)g_support;
    float4 acc = __ldg(&((const float4*)bias)[lane]);

    for (int i = start; i < end; i += 32) {
        int n = end - i;
        if (n > 32) n = 32;
        uint2 em = make_uint2(0u, 0u);
        if (lane < n) em = g_edges[i + lane];
        for (int j = 0; j < n; j++) {
            unsigned s = __shfl_sync(0xFFFFFFFFu, em.x, j);
            float    w = __uint_as_float(__shfl_sync(0xFFFFFFFFu, em.y, j));
            float4 v = sup4[(size_t)s * (D / 4) + lane];
            acc.x += w * v.x;
            acc.y += w * v.y;
            acc.z += w * v.z;
            acc.w += w * v.w;
        }
    }
    ((float4*)out)[(size_t)warp * (D / 4) + lane] = acc;
}

// ---------------------------------------------------------------------------
// Launch with fork/join (R7 topology — the proven-legal resource pattern:
// exactly 1 side stream + 2 events, created per call, never cached).
// ---------------------------------------------------------------------------
extern "C" void kernel_launch(void* const* d_in, const int* in_sizes, int n_in,
                              void* d_out, int out_size)
{
    const float* x    = (const float*)d_in[0];
    const int*   esrc = (const int*)d_in[1];
    const int*   edst = (const int*)d_in[2];
    const float* ew   = (const float*)d_in[3];
    const float* W    = (const float*)d_in[4];
    const float* bias = (const float*)d_in[5];
    float* out = (float*)d_out;

    void* countPtr;
    cudaGetSymbolAddress(&countPtr, g_count);
    float* support;
    cudaGetSymbolAddress((void**)&support, g_support);

    cudaStream_t main_s = 0;
    cudaStream_t side_s;
    cudaStreamCreateWithFlags(&side_s, cudaStreamNonBlocking);
    cudaEvent_t ev_fork, ev_join;
    cudaEventCreateWithFlags(&ev_fork, cudaEventDisableTiming);
    cudaEventCreateWithFlags(&ev_join, cudaEventDisableTiming);

    // ---- fork ----
    cudaEventRecord(ev_fork, main_s);
    cudaStreamWaitEvent(side_s, ev_fork, 0);

    // side stream: CSR build chain
    cudaMemsetAsync(countPtr, 0, N_NODES * sizeof(int), side_s);
    hist_kernel<<<1024, 256, 0, side_s>>>(edst);
    scan1_kernel<<<NB_SCAN, SCAN_BLOCK, 0, side_s>>>();
    scan2_kernel<<<1, 256, 0, side_s>>>();
    scan3_kernel<<<NB_SCAN, SCAN_BLOCK, 0, side_s>>>();
    scatter_kernel<<<1024, 256, 0, side_s>>>(esrc, edst, ew);
    cudaEventRecord(ev_join, side_s);

    // main stream: persistent GEMM (W loaded once per CTA, x prefetched)
    {
        static const int smem_bytes = (D * D + TILE_M * D) * (int)sizeof(float); // 96 KB
        cudaFuncSetAttribute(gemm_persist_kernel,
                             cudaFuncAttributeMaxDynamicSharedMemorySize, smem_bytes);
        gemm_persist_kernel<<<PERSIST_BLOCKS, 256, smem_bytes, main_s>>>(x, W, support);
    }

    // ---- join ----
    cudaStreamWaitEvent(main_s, ev_join, 0);

    // gather SpMM + bias
    {
        int warps_per_block = 8;
        int blocks = (N_NODES + warps_per_block - 1) / warps_per_block;
        gather_kernel<<<blocks, 256, 0, main_s>>>(bias, out);
    }
}